// round 5
// baseline (speedup 1.0000x reference)
#include <cuda_runtime.h>
#include <cuda_bf16.h>

// PosMLP split into two kernels:
//  A) gen_weights: weights[q][65] = queries[q] @ w_gen^T + b_gen   (into __device__ scratch)
//  B) raster:      per-(q,w) thread walks 48 rows of the 16-wide ReLU MLP,
//                  using packed fma.rn.f32x2 (FFMA2) to halve fma-pipe traffic.
//
// Shapes fixed by setup_inputs: B=2, Q=900 (NQ=1800), C=256, HIDDEN=16, H=W=48.

#define CC   256
#define NW   65
#define HD   16
#define HH   48
#define WW   48
#define NQ   1800

__device__ float g_wt[NQ * NW];   // 468 KB scratch (L2-resident)

// ---------------------------------------------------------------------------
// Kernel A: warp-per-query GEMM. 225 blocks x 256 threads (8 warps = 8 queries).
// Lane owns channels [lane*8, lane*8+8) via two float4 loads (coalesced 128b).
// ---------------------------------------------------------------------------
__global__ __launch_bounds__(256) void gen_weights_kernel(
    const float* __restrict__ queries,   // [1800][256]
    const float* __restrict__ w_gen,     // [65][256]
    const float* __restrict__ b_gen)     // [65]
{
    const int warp = threadIdx.x >> 5;
    const int lane = threadIdx.x & 31;
    const int q    = blockIdx.x * 8 + warp;      // 225*8 = 1800 exactly

    const float4* qrow = (const float4*)(queries + (size_t)q * CC);
    const float4  q0 = qrow[lane * 2];
    const float4  q1 = qrow[lane * 2 + 1];

    #pragma unroll 5
    for (int n = 0; n < NW; n++) {
        const float4* wrow = (const float4*)(w_gen + (size_t)n * CC);
        const float4 w0 = wrow[lane * 2];
        const float4 w1 = wrow[lane * 2 + 1];
        // two accumulator chains for ILP
        float s0 = 0.f, s1 = 0.f;
        s0 = fmaf(q0.x, w0.x, s0);  s1 = fmaf(q0.y, w0.y, s1);
        s0 = fmaf(q0.z, w0.z, s0);  s1 = fmaf(q0.w, w0.w, s1);
        s0 = fmaf(q1.x, w1.x, s0);  s1 = fmaf(q1.y, w1.y, s1);
        s0 = fmaf(q1.z, w1.z, s0);  s1 = fmaf(q1.w, w1.w, s1);
        float s = s0 + s1;
        #pragma unroll
        for (int off = 16; off > 0; off >>= 1)
            s += __shfl_xor_sync(0xffffffffu, s, off);
        if (lane == 0)
            g_wt[q * NW + n] = s + b_gen[n];
    }
}

// ---------------------------------------------------------------------------
// Packed fp32x2 FMA (sm_103a FFMA2 — only reachable via PTX fma.rn.f32x2).
// ---------------------------------------------------------------------------
union F2U { float2 f; unsigned long long u; };

__device__ __forceinline__ float2 ffma2(float2 a, float2 b, float2 c) {
    F2U A, B, C, D;
    A.f = a; B.f = b; C.f = c;
    asm("fma.rn.f32x2 %0, %1, %2, %3;"
        : "=l"(D.u) : "l"(A.u), "l"(B.u), "l"(C.u));
    return D.f;
}

// ---------------------------------------------------------------------------
// Kernel B: rasterizer. Flat thread -> (q, w). 675 blocks x 128 threads = 86400.
// Per row: 1 FFMA2 (v) + 2 FMNMX (alu) + 1 FFMA2 (acc) per 2 hidden units
// => 16 fma-pipe inst + 16 alu inst per row per thread.
// ---------------------------------------------------------------------------
__global__ __launch_bounds__(128) void raster_kernel(
    const float* __restrict__ pos,       // [1800][4] (cx, cy, bw, bh)
    float* __restrict__ out)             // [1800][48][48]
{
    const int gtid = blockIdx.x * 128 + threadIdx.x;
    const int q    = gtid / WW;
    const int w    = gtid - q * WW;

    const float* __restrict__ wt = g_wt + q * NW;

    const float cx = pos[q * 4 + 0];
    const float cy = pos[q * 4 + 1];
    const float bw = pos[q * 4 + 2];
    const float bh = pos[q * 4 + 3];

    const float rx     = ((w + 0.5f) * (1.0f / WW) - cx) / bw;
    const float inv_bh = 1.0f / bh;

    // Pack per-pair (k = 2j, 2j+1) params. Fold rx*w1x + b1 into tw.
    float2 w1y2[HD / 2], tw2[HD / 2], w22[HD / 2];
    const float2 rx2 = make_float2(rx, rx);
    #pragma unroll
    for (int j = 0; j < HD / 2; j++) {
        w1y2[j]      = make_float2(wt[4 * j],     wt[4 * j + 2]);     // w1y_{2j}, w1y_{2j+1}
        float2 w1x2  = make_float2(wt[4 * j + 1], wt[4 * j + 3]);     // w1x_{2j}, w1x_{2j+1}
        float2 b12   = make_float2(wt[2 * HD + 2 * j], wt[2 * HD + 2 * j + 1]);
        tw2[j]       = ffma2(rx2, w1x2, b12);
        w22[j]       = make_float2(wt[3 * HD + 2 * j], wt[3 * HD + 2 * j + 1]);
    }
    const float b2 = wt[4 * HD];

    const float y0    = (0.5f * (1.0f / HH) - cy) * inv_bh;
    const float ystep = (1.0f / HH) * inv_bh;

    float* obase = out + (size_t)q * (HH * WW) + w;

    #pragma unroll 2
    for (int h = 0; h < HH; h++) {
        const float  ry  = fmaf((float)h, ystep, y0);
        const float2 ry2 = make_float2(ry, ry);
        float2 acc0 = make_float2(b2, 0.f);
        float2 acc1 = make_float2(0.f, 0.f);
        #pragma unroll
        for (int j = 0; j < HD / 2; j += 2) {
            float2 v0 = ffma2(ry2, w1y2[j],     tw2[j]);
            float2 v1 = ffma2(ry2, w1y2[j + 1], tw2[j + 1]);
            v0.x = fmaxf(v0.x, 0.f);  v0.y = fmaxf(v0.y, 0.f);
            v1.x = fmaxf(v1.x, 0.f);  v1.y = fmaxf(v1.y, 0.f);
            acc0 = ffma2(v0, w22[j],     acc0);
            acc1 = ffma2(v1, w22[j + 1], acc1);
        }
        obase[h * WW] = (acc0.x + acc0.y) + (acc1.x + acc1.y);
    }
}

extern "C" void kernel_launch(void* const* d_in, const int* in_sizes, int n_in,
                              void* d_out, int out_size) {
    const float* queries = (const float*)d_in[0];
    const float* pos     = (const float*)d_in[1];
    const float* w_gen   = (const float*)d_in[2];
    const float* b_gen   = (const float*)d_in[3];
    float* out = (float*)d_out;

    gen_weights_kernel<<<NQ / 8, 256>>>(queries, w_gen, b_gen);
    raster_kernel<<<(NQ * WW) / 128, 128>>>(pos, out);
}

// round 6
// speedup vs baseline: 1.2133x; 1.2133x over previous
#include <cuda_runtime.h>
#include <cuda_bf16.h>

// PosMLP, two kernels:
//  A) gen_weights: weights[q][65] = queries[q] @ w_gen^T + b_gen -> __device__ scratch.
//     4 warps per query (n strided by 4) for 7200 warps (~48/SM) of latency hiding.
//  B) raster: thread = (q, w, h-half); 24 rows each; packed fma.rn.f32x2 inner loop.
//     172800 threads / 1350 blocks (~33 warps/SM).
//
// Shapes fixed by setup_inputs: B=2, Q=900 (NQ=1800), C=256, HIDDEN=16, H=W=48.

#define CC   256
#define NW   65
#define HD   16
#define HH   48
#define WW   48
#define NQ   1800

__device__ float g_wt[NQ * NW];   // 468 KB scratch (L2-resident)

// ---------------------------------------------------------------------------
// Kernel A: 4 warps per query. 900 blocks x 256 threads (8 warps).
// Warp (q, ns) computes n = ns, ns+4, ... . Lane owns channels [lane*8, lane*8+8).
// ---------------------------------------------------------------------------
__global__ __launch_bounds__(256) void gen_weights_kernel(
    const float* __restrict__ queries,   // [1800][256]
    const float* __restrict__ w_gen,     // [65][256]
    const float* __restrict__ b_gen)     // [65]
{
    const int warp = threadIdx.x >> 5;
    const int lane = threadIdx.x & 31;
    const int gw   = blockIdx.x * 8 + warp;   // 0..7199
    const int q    = gw >> 2;
    const int ns   = gw & 3;

    const float4* qrow = (const float4*)(queries + (size_t)q * CC);
    const float4  q0 = qrow[lane * 2];
    const float4  q1 = qrow[lane * 2 + 1];

    for (int n = ns; n < NW; n += 4) {
        const float4* wrow = (const float4*)(w_gen + (size_t)n * CC);
        const float4 w0 = wrow[lane * 2];
        const float4 w1 = wrow[lane * 2 + 1];
        float s0 = 0.f, s1 = 0.f;
        s0 = fmaf(q0.x, w0.x, s0);  s1 = fmaf(q0.y, w0.y, s1);
        s0 = fmaf(q0.z, w0.z, s0);  s1 = fmaf(q0.w, w0.w, s1);
        s0 = fmaf(q1.x, w1.x, s0);  s1 = fmaf(q1.y, w1.y, s1);
        s0 = fmaf(q1.z, w1.z, s0);  s1 = fmaf(q1.w, w1.w, s1);
        float s = s0 + s1;
        #pragma unroll
        for (int off = 16; off > 0; off >>= 1)
            s += __shfl_xor_sync(0xffffffffu, s, off);
        if (lane == 0)
            g_wt[q * NW + n] = s + b_gen[n];
    }
}

// ---------------------------------------------------------------------------
// Packed fp32x2 FMA (sm_103a FFMA2 — only reachable via PTX fma.rn.f32x2).
// ---------------------------------------------------------------------------
union F2U { float2 f; unsigned long long u; };

__device__ __forceinline__ float2 ffma2(float2 a, float2 b, float2 c) {
    F2U A, B, C, D;
    A.f = a; B.f = b; C.f = c;
    asm("fma.rn.f32x2 %0, %1, %2, %3;"
        : "=l"(D.u) : "l"(A.u), "l"(B.u), "l"(C.u));
    return D.f;
}

// ---------------------------------------------------------------------------
// Kernel B: rasterizer, h-split in halves. 1350 blocks x 128 threads.
// gtid -> q = gtid/96; rem = gtid%96; hh = rem/48 (row half); w = rem%48.
// Per row: 8 FFMA2 (v) + 16 FMNMX (alu) + 8 FFMA2 (acc); 4 scalar acc chains.
// ---------------------------------------------------------------------------
__global__ __launch_bounds__(128) void raster_kernel(
    const float* __restrict__ pos,       // [1800][4] (cx, cy, bw, bh)
    float* __restrict__ out)             // [1800][48][48]
{
    const int gtid = blockIdx.x * 128 + threadIdx.x;
    const int q    = gtid / 96;
    const int rem  = gtid - q * 96;
    const int hh   = rem / 48;           // 0 or 1
    const int w    = rem - hh * 48;

    const float* __restrict__ wt = g_wt + q * NW;

    const float cx = pos[q * 4 + 0];
    const float cy = pos[q * 4 + 1];
    const float bw = pos[q * 4 + 2];
    const float bh = pos[q * 4 + 3];

    const float rx     = ((w + 0.5f) * (1.0f / WW) - cx) / bw;
    const float inv_bh = 1.0f / bh;

    // Pack per-pair (k = 2j, 2j+1) params. Fold rx*w1x + b1 into tw.
    float2 w1y2[HD / 2], tw2[HD / 2], w22[HD / 2];
    const float2 rx2 = make_float2(rx, rx);
    #pragma unroll
    for (int j = 0; j < HD / 2; j++) {
        w1y2[j]     = make_float2(wt[4 * j],     wt[4 * j + 2]);      // w1y_{2j}, w1y_{2j+1}
        float2 w1x2 = make_float2(wt[4 * j + 1], wt[4 * j + 3]);      // w1x_{2j}, w1x_{2j+1}
        float2 b12  = make_float2(wt[2 * HD + 2 * j], wt[2 * HD + 2 * j + 1]);
        tw2[j]      = ffma2(rx2, w1x2, b12);
        w22[j]      = make_float2(wt[3 * HD + 2 * j], wt[3 * HD + 2 * j + 1]);
    }
    const float b2 = wt[4 * HD];

    const int   h0    = hh * (HH / 2);
    const float y0    = ((h0 + 0.5f) * (1.0f / HH) - cy) * inv_bh;
    const float ystep = (1.0f / HH) * inv_bh;

    float* obase = out + (size_t)q * (HH * WW) + h0 * WW + w;

    #pragma unroll 6
    for (int h = 0; h < HH / 2; h++) {
        const float  ry  = fmaf((float)h, ystep, y0);
        const float2 ry2 = make_float2(ry, ry);
        float2 acc0 = make_float2(b2, 0.f);
        float2 acc1 = make_float2(0.f, 0.f);
        #pragma unroll
        for (int j = 0; j < HD / 2; j += 2) {
            float2 v0 = ffma2(ry2, w1y2[j],     tw2[j]);
            float2 v1 = ffma2(ry2, w1y2[j + 1], tw2[j + 1]);
            v0.x = fmaxf(v0.x, 0.f);  v0.y = fmaxf(v0.y, 0.f);
            v1.x = fmaxf(v1.x, 0.f);  v1.y = fmaxf(v1.y, 0.f);
            acc0 = ffma2(v0, w22[j],     acc0);
            acc1 = ffma2(v1, w22[j + 1], acc1);
        }
        obase[h * WW] = (acc0.x + acc0.y) + (acc1.x + acc1.y);
    }
}

extern "C" void kernel_launch(void* const* d_in, const int* in_sizes, int n_in,
                              void* d_out, int out_size) {
    const float* queries = (const float*)d_in[0];
    const float* pos     = (const float*)d_in[1];
    const float* w_gen   = (const float*)d_in[2];
    const float* b_gen   = (const float*)d_in[3];
    float* out = (float*)d_out;

    gen_weights_kernel<<<900, 256>>>(queries, w_gen, b_gen);
    raster_kernel<<<(NQ * WW * 2) / 128, 128>>>(pos, out);
}